// round 1
// baseline (speedup 1.0000x reference)
#include <cuda_runtime.h>
#include <cuda_bf16.h>

#define NTOK 2048
#define HDIM 1024
#define IDIM 2048
#define NEXP 8
#define TOPK 2
#define NK (NTOK*TOPK)

// ---------------- scratch (device globals; no allocation allowed) ----------------
__device__ int   g_ctr[2*NEXP];              // [0:8) counts, [8:16) assign cursors
__device__ int   g_offsets[NEXP+1];
__device__ int   g_topk_idx[NK];
__device__ float g_topk_w[NK];
__device__ int   g_perm_tok[NK];             // slot -> token
__device__ int   g_slot_of[NK];              // (token*K+k) -> slot
__device__ float g_mid[(size_t)NK*IDIM];     // 32 MB: silu(gate)*up, expert-sorted rows
__device__ float g_down[(size_t)NK*HDIM];    // 16 MB: down-proj per slot

// ---------------- router: one warp per token ----------------
__global__ void router_kernel(const float* __restrict__ x, const float* __restrict__ Wr) {
    int warp = (blockIdx.x * blockDim.x + threadIdx.x) >> 5;
    int lane = threadIdx.x & 31;
    if (warp >= NTOK) return;
    const float* xr = x + (size_t)warp * HDIM;
    float acc[NEXP];
#pragma unroll
    for (int e = 0; e < NEXP; e++) acc[e] = 0.f;
    for (int h = lane; h < HDIM; h += 32) {
        float xv = xr[h];
#pragma unroll
        for (int e = 0; e < NEXP; e++) acc[e] += xv * Wr[e*HDIM + h];
    }
#pragma unroll
    for (int e = 0; e < NEXP; e++) {
#pragma unroll
        for (int off = 16; off > 0; off >>= 1)
            acc[e] += __shfl_xor_sync(0xFFFFFFFFu, acc[e], off);
    }
    if (lane == 0) {
        // top-2 of logits == top-2 of softmax probs (monotone); ties -> lowest index (matches jax top_k)
        int i0 = 0; float v0 = acc[0];
#pragma unroll
        for (int e = 1; e < NEXP; e++) if (acc[e] > v0) { v0 = acc[e]; i0 = e; }
        int i1 = -1; float v1 = -1e30f;
#pragma unroll
        for (int e = 0; e < NEXP; e++) if (e != i0 && acc[e] > v1) { v1 = acc[e]; i1 = e; }
        // renormalized top-2 softmax weights: softmax denominator cancels
        float r = __expf(v1 - v0);           // v0 is the max -> stable
        float inv = 1.f / (1.f + r);
        g_topk_idx[2*warp]   = i0;  g_topk_w[2*warp]   = inv;
        g_topk_idx[2*warp+1] = i1;  g_topk_w[2*warp+1] = r * inv;
        atomicAdd(&g_ctr[i0], 1);
        atomicAdd(&g_ctr[i1], 1);
    }
}

// ---------------- scan + aux loss ----------------
__global__ void scan_kernel(float* __restrict__ aux_out) {
    if (threadIdx.x != 0) return;
    int off = 0;
#pragma unroll
    for (int e = 0; e < NEXP; e++) { g_offsets[e] = off; off += g_ctr[e]; }
    g_offsets[NEXP] = off;
    if (aux_out) {
        // counts.mean(axis=0) = c_e/N ; mean over experts = K/E exactly (sum c_e = N*K)
        float mean = (float)TOPK / (float)NEXP;
        float var = 0.f;
#pragma unroll
        for (int e = 0; e < NEXP; e++) {
            float v = (float)g_ctr[e] / (float)NTOK - mean;
            var += v * v;
        }
        *aux_out = var / (float)(NEXP - 1) * (float)NEXP;  // ddof=1, * E
    }
}

// ---------------- slot assignment (expert-major permutation) ----------------
__global__ void assign_kernel() {
    int tk = blockIdx.x * blockDim.x + threadIdx.x;
    if (tk >= NK) return;
    int e = g_topk_idx[tk];
    int pos = g_offsets[e] + atomicAdd(&g_ctr[NEXP + e], 1);
    g_perm_tok[pos] = tk >> 1;
    g_slot_of[tk] = pos;
}

// ---------------- gate+up grouped GEMM (shared A), fused SiLU*up ----------------
// tile 64x64x16, 256 threads, 4x4 microtiles, two B operands
__global__ __launch_bounds__(256) void gateup_kernel(
    const float* __restrict__ x, const float* __restrict__ Wg, const float* __restrict__ Wu) {
    const int e = blockIdx.z;
    const int seg0 = g_offsets[e];
    const int segLen = g_offsets[e+1] - seg0;
    const int m0 = blockIdx.y * 64;
    if (m0 >= segLen) return;
    const int n0 = blockIdx.x * 64;

    __shared__ float As[16][68];
    __shared__ float Bg[16][68];
    __shared__ float Bu[16][68];

    const int t = threadIdx.x;
    const int tm = t >> 4, tn = t & 15;

    int ltok[4];
#pragma unroll
    for (int it = 0; it < 4; it++) {
        int s = m0 + it*16 + tm;
        ltok[it] = (s < segLen) ? g_perm_tok[seg0 + s] : -1;
    }
    const float* WgE = Wg + (size_t)e * IDIM * HDIM;
    const float* WuE = Wu + (size_t)e * IDIM * HDIM;

    float ag[4][4] = {}, au[4][4] = {};

    for (int k0 = 0; k0 < HDIM; k0 += 16) {
#pragma unroll
        for (int it = 0; it < 4; it++) {
            int mm = it*16 + tm;   // row/col index within tile; lanes vary tn -> coalesced 64B chunks
            As[tn][mm] = (ltok[it] >= 0) ? x[(size_t)ltok[it]*HDIM + k0 + tn] : 0.f;
            Bg[tn][mm] = WgE[(size_t)(n0 + mm)*HDIM + k0 + tn];
            Bu[tn][mm] = WuE[(size_t)(n0 + mm)*HDIM + k0 + tn];
        }
        __syncthreads();
#pragma unroll
        for (int kk = 0; kk < 16; kk++) {
            float4 av  = *reinterpret_cast<const float4*>(&As[kk][tm*4]);
            float4 bgv = *reinterpret_cast<const float4*>(&Bg[kk][tn*4]);
            float4 buv = *reinterpret_cast<const float4*>(&Bu[kk][tn*4]);
            const float a[4]  = {av.x, av.y, av.z, av.w};
            const float bg[4] = {bgv.x, bgv.y, bgv.z, bgv.w};
            const float bu[4] = {buv.x, buv.y, buv.z, buv.w};
#pragma unroll
            for (int i = 0; i < 4; i++)
#pragma unroll
                for (int j = 0; j < 4; j++) {
                    ag[i][j] += a[i] * bg[j];
                    au[i][j] += a[i] * bu[j];
                }
        }
        __syncthreads();
    }

#pragma unroll
    for (int i = 0; i < 4; i++) {
        int s = m0 + tm*4 + i;
        if (s < segLen) {
            float4 o;
            float v[4];
#pragma unroll
            for (int j = 0; j < 4; j++) {
                float g = ag[i][j];
                v[j] = au[i][j] * (g / (1.f + __expf(-g)));   // silu(g)*u
            }
            o.x = v[0]; o.y = v[1]; o.z = v[2]; o.w = v[3];
            *reinterpret_cast<float4*>(&g_mid[(size_t)(seg0+s)*IDIM + n0 + tn*4]) = o;
        }
    }
}

// ---------------- down grouped GEMM ----------------
__global__ __launch_bounds__(256) void down_kernel(const float* __restrict__ Wd) {
    const int e = blockIdx.z;
    const int seg0 = g_offsets[e];
    const int segLen = g_offsets[e+1] - seg0;
    const int m0 = blockIdx.y * 64;
    if (m0 >= segLen) return;
    const int n0 = blockIdx.x * 64;

    __shared__ float As[16][68];
    __shared__ float Bs[16][68];

    const int t = threadIdx.x;
    const int tm = t >> 4, tn = t & 15;
    const float* WdE = Wd + (size_t)e * HDIM * IDIM;

    float acc[4][4] = {};

    for (int k0 = 0; k0 < IDIM; k0 += 16) {
#pragma unroll
        for (int it = 0; it < 4; it++) {
            int mm = it*16 + tm;
            int s = m0 + mm;
            As[tn][mm] = (s < segLen) ? g_mid[(size_t)(seg0+s)*IDIM + k0 + tn] : 0.f;
            Bs[tn][mm] = WdE[(size_t)(n0 + mm)*IDIM + k0 + tn];
        }
        __syncthreads();
#pragma unroll
        for (int kk = 0; kk < 16; kk++) {
            float4 av = *reinterpret_cast<const float4*>(&As[kk][tm*4]);
            float4 bv = *reinterpret_cast<const float4*>(&Bs[kk][tn*4]);
            const float a[4] = {av.x, av.y, av.z, av.w};
            const float b[4] = {bv.x, bv.y, bv.z, bv.w};
#pragma unroll
            for (int i = 0; i < 4; i++)
#pragma unroll
                for (int j = 0; j < 4; j++)
                    acc[i][j] += a[i] * b[j];
        }
        __syncthreads();
    }

#pragma unroll
    for (int i = 0; i < 4; i++) {
        int s = m0 + tm*4 + i;
        if (s < segLen) {
            float4 o = {acc[i][0], acc[i][1], acc[i][2], acc[i][3]};
            *reinterpret_cast<float4*>(&g_down[(size_t)(seg0+s)*HDIM + n0 + tn*4]) = o;
        }
    }
}

// ---------------- weighted combine (atomic-free, deterministic) ----------------
__global__ void combine_kernel(float* __restrict__ out) {
    int idx = blockIdx.x * blockDim.x + threadIdx.x;
    if (idx >= NTOK * (HDIM/4)) return;
    int n = idx / (HDIM/4);
    int h = (idx % (HDIM/4)) * 4;
    float w0 = g_topk_w[2*n], w1 = g_topk_w[2*n+1];
    int s0 = g_slot_of[2*n], s1 = g_slot_of[2*n+1];
    float4 a = *reinterpret_cast<const float4*>(&g_down[(size_t)s0*HDIM + h]);
    float4 b = *reinterpret_cast<const float4*>(&g_down[(size_t)s1*HDIM + h]);
    float4 o;
    o.x = w0*a.x + w1*b.x;
    o.y = w0*a.y + w1*b.y;
    o.z = w0*a.z + w1*b.z;
    o.w = w0*a.w + w1*b.w;
    *reinterpret_cast<float4*>(&out[(size_t)n*HDIM + h]) = o;
}

// ---------------- launch ----------------
extern "C" void kernel_launch(void* const* d_in, const int* in_sizes, int n_in,
                              void* d_out, int out_size) {
    const float* x  = (const float*)d_in[0];
    const float* Wr = (const float*)d_in[1];
    const float* Wg = (const float*)d_in[2];
    const float* Wu = (const float*)d_in[3];
    const float* Wd = (const float*)d_in[4];
    float* out = (float*)d_out;

    void* ctr_ptr = nullptr;
    cudaGetSymbolAddress(&ctr_ptr, g_ctr);
    cudaMemsetAsync(ctr_ptr, 0, sizeof(int)*2*NEXP, 0);

    router_kernel<<<NTOK/8, 256>>>(x, Wr);

    float* aux_out = (out_size > NTOK*HDIM) ? (out + (size_t)NTOK*HDIM) : nullptr;
    scan_kernel<<<1, 32>>>(aux_out);

    assign_kernel<<<(NK + 255)/256, 256>>>();

    gateup_kernel<<<dim3(IDIM/64, NTOK/64, NEXP), 256>>>(x, Wg, Wu);
    down_kernel<<<dim3(HDIM/64, NTOK/64, NEXP), 256>>>(Wd);

    combine_kernel<<<(NTOK*(HDIM/4) + 255)/256, 256>>>(out);
}

// round 3
// speedup vs baseline: 1.8243x; 1.8243x over previous
#include <cuda_runtime.h>
#include <cuda_bf16.h>
#include <stdint.h>

#define NTOK 2048
#define HDIM 1024
#define IDIM 2048
#define NEXP 8
#define TOPK 2
#define NK (NTOK*TOPK)

// ---------------- scratch (device globals) ----------------
__device__ int   g_ctr[2*NEXP];
__device__ int   g_offsets[NEXP+1];
__device__ int   g_topk_idx[NK];
__device__ float g_topk_w[NK];
__device__ int   g_perm_tok[NK];
__device__ int   g_slot_of[NK];
__device__ __nv_bfloat16 g_mid_hi[(size_t)(NK+128)*IDIM];
__device__ __nv_bfloat16 g_mid_lo[(size_t)(NK+128)*IDIM];
__device__ float g_down[(size_t)(NK+128)*HDIM];

// ---------------- helpers ----------------
__device__ __forceinline__ uint32_t smem_u32(const void* p){
    uint32_t a;
    asm("{ .reg .u64 t; cvta.to.shared.u64 t, %1; cvt.u32.u64 %0, t; }" : "=r"(a) : "l"(p));
    return a;
}
// swizzled 16B-chunk offset within a 128-row x 32-col bf16 tile (64B rows)
#define SWZ(row, c) ((uint32_t)(row)*64u + ((((uint32_t)(c)) ^ ((((uint32_t)(row))>>1)&3u))<<4))

#define CPA16(dst, src, sz) \
    asm volatile("cp.async.cg.shared.global [%0], [%1], 16, %2;" \
                 :: "r"(dst), "l"(src), "r"(sz))
#define CPA_COMMIT() asm volatile("cp.async.commit_group;")
#define CPA_WAIT0()  asm volatile("cp.async.wait_group 0;")

#define LDSM4(r0,r1,r2,r3,addr) \
    asm volatile("ldmatrix.sync.aligned.m8n8.x4.shared.b16 {%0,%1,%2,%3}, [%4];" \
                 : "=r"(r0),"=r"(r1),"=r"(r2),"=r"(r3) : "r"(addr))

#define MMA_BF16(d, a, b0, b1) \
    asm volatile("mma.sync.aligned.m16n8k16.row.col.f32.bf16.bf16.f32 " \
        "{%0,%1,%2,%3}, {%4,%5,%6,%7}, {%8,%9}, {%0,%1,%2,%3};" \
        : "+f"((d)[0]), "+f"((d)[1]), "+f"((d)[2]), "+f"((d)[3]) \
        : "r"((a)[0]), "r"((a)[1]), "r"((a)[2]), "r"((a)[3]), "r"(b0), "r"(b1))

__device__ __forceinline__ void splitf4(float4 v, uint2& hi, uint2& lo){
    __nv_bfloat162 h01 = __float22bfloat162_rn(make_float2(v.x, v.y));
    __nv_bfloat162 h23 = __float22bfloat162_rn(make_float2(v.z, v.w));
    float2 f01 = __bfloat1622float2(h01), f23 = __bfloat1622float2(h23);
    __nv_bfloat162 l01 = __float22bfloat162_rn(make_float2(v.x - f01.x, v.y - f01.y));
    __nv_bfloat162 l23 = __float22bfloat162_rn(make_float2(v.z - f23.x, v.w - f23.y));
    hi = make_uint2(*reinterpret_cast<uint32_t*>(&h01), *reinterpret_cast<uint32_t*>(&h23));
    lo = make_uint2(*reinterpret_cast<uint32_t*>(&l01), *reinterpret_cast<uint32_t*>(&l23));
}

// ---------------- router ----------------
__global__ void router_kernel(const float* __restrict__ x, const float* __restrict__ Wr) {
    int warp = (blockIdx.x * blockDim.x + threadIdx.x) >> 5;
    int lane = threadIdx.x & 31;
    if (warp >= NTOK) return;
    const float* xr = x + (size_t)warp * HDIM;
    float acc[NEXP];
#pragma unroll
    for (int e = 0; e < NEXP; e++) acc[e] = 0.f;
    for (int h = lane; h < HDIM; h += 32) {
        float xv = xr[h];
#pragma unroll
        for (int e = 0; e < NEXP; e++) acc[e] += xv * Wr[e*HDIM + h];
    }
#pragma unroll
    for (int e = 0; e < NEXP; e++) {
#pragma unroll
        for (int off = 16; off > 0; off >>= 1)
            acc[e] += __shfl_xor_sync(0xFFFFFFFFu, acc[e], off);
    }
    if (lane == 0) {
        int i0 = 0; float v0 = acc[0];
#pragma unroll
        for (int e = 1; e < NEXP; e++) if (acc[e] > v0) { v0 = acc[e]; i0 = e; }
        int i1 = -1; float v1 = -1e30f;
#pragma unroll
        for (int e = 0; e < NEXP; e++) if (e != i0 && acc[e] > v1) { v1 = acc[e]; i1 = e; }
        float r = __expf(v1 - v0);
        float inv = 1.f / (1.f + r);
        g_topk_idx[2*warp]   = i0;  g_topk_w[2*warp]   = inv;
        g_topk_idx[2*warp+1] = i1;  g_topk_w[2*warp+1] = r * inv;
        atomicAdd(&g_ctr[i0], 1);
        atomicAdd(&g_ctr[i1], 1);
    }
}

// ---------------- scan + aux ----------------
__global__ void scan_kernel(float* __restrict__ aux_out) {
    if (threadIdx.x != 0) return;
    int off = 0;
#pragma unroll
    for (int e = 0; e < NEXP; e++) { g_offsets[e] = off; off += g_ctr[e]; }
    g_offsets[NEXP] = off;
    if (aux_out) {
        float mean = (float)TOPK / (float)NEXP;
        float var = 0.f;
#pragma unroll
        for (int e = 0; e < NEXP; e++) {
            float v = (float)g_ctr[e] / (float)NTOK - mean;
            var += v * v;
        }
        *aux_out = var / (float)(NEXP - 1) * (float)NEXP;
    }
}

// ---------------- slot assignment ----------------
__global__ void assign_kernel() {
    int tk = blockIdx.x * blockDim.x + threadIdx.x;
    if (tk >= NK) return;
    int e = g_topk_idx[tk];
    int pos = g_offsets[e] + atomicAdd(&g_ctr[NEXP + e], 1);
    g_perm_tok[pos] = tk >> 1;
    g_slot_of[tk] = pos;
}

// ---------------- gate+up bf16x3 mma GEMM ----------------
#define GU_TAH 0
#define GU_TAL 8192
#define GU_TGH 16384
#define GU_TGL 24576
#define GU_TUH 32768
#define GU_TUL 40960
#define GU_F32 49152
#define GU_FSTRIDE 55296      // 3 tiles * 128 rows * 144B
#define GU_FA 0
#define GU_FG 18432
#define GU_FU 36864
#define GU_SMEM (GU_F32 + 2*GU_FSTRIDE)   // 159744

__global__ __launch_bounds__(256,1) void gateup_mma(
        const float* __restrict__ x,
        const float* __restrict__ Wg, const float* __restrict__ Wu) {
    const int e = blockIdx.z;
    const int seg0 = g_offsets[e];
    const int segLen = g_offsets[e+1] - seg0;
    const int m0 = blockIdx.y * 128;
    if (m0 >= segLen) return;
    const int n0 = blockIdx.x * 128;

    extern __shared__ char smc[];
    const uint32_t sb = smem_u32(smc);
    const int t = threadIdx.x, lane = t & 31, wid = t >> 5;
    const int wm = wid >> 2, wn = wid & 3;
    const int r = t & 127, half = t >> 7;

    int rowtok = (m0 + r < segLen) ? g_perm_tok[seg0 + m0 + r] : -1;
    const float* srcA = x + (size_t)(rowtok >= 0 ? rowtok : 0)*HDIM + half*16;
    const int szA = (rowtok >= 0) ? 16 : 0;
    const float* srcG = Wg + ((size_t)e*IDIM + n0 + r)*HDIM + half*16;
    const float* srcU = Wu + ((size_t)e*IDIM + n0 + r)*HDIM + half*16;
    const uint32_t frow = r*144 + half*64;

    float cg[4][4][4] = {}, cu[4][4][4] = {};

    // issue stage 0
    {
        uint32_t fb = sb + GU_F32 + frow;
#pragma unroll
        for (int q = 0; q < 4; q++) CPA16(fb + GU_FA + q*16, srcA + q*4, szA);
#pragma unroll
        for (int q = 0; q < 4; q++) CPA16(fb + GU_FG + q*16, srcG + q*4, 16);
#pragma unroll
        for (int q = 0; q < 4; q++) CPA16(fb + GU_FU + q*16, srcU + q*4, 16);
        CPA_COMMIT();
    }

#pragma unroll 1
    for (int s = 0; s < 32; ++s) {
        const int b = s & 1;
        CPA_WAIT0();
        __syncthreads();
        if (s < 31) {
            const int k0 = (s+1)*32;
            uint32_t fb = sb + GU_F32 + (b^1)*GU_FSTRIDE + frow;
#pragma unroll
            for (int q = 0; q < 4; q++) CPA16(fb + GU_FA + q*16, srcA + k0 + q*4, szA);
#pragma unroll
            for (int q = 0; q < 4; q++) CPA16(fb + GU_FG + q*16, srcG + k0 + q*4, 16);
#pragma unroll
            for (int q = 0; q < 4; q++) CPA16(fb + GU_FU + q*16, srcU + k0 + q*4, 16);
            CPA_COMMIT();
        }
        // convert fp32 stage -> swizzled bf16 hi/lo tiles
        {
            const char* fp = smc + GU_F32 + b*GU_FSTRIDE + frow;
            const int fo[3] = {GU_FA, GU_FG, GU_FU};
            const int ho[3] = {GU_TAH, GU_TGH, GU_TUH};
            const int lo_[3] = {GU_TAL, GU_TGL, GU_TUL};
#pragma unroll
            for (int tt = 0; tt < 3; tt++) {
#pragma unroll
                for (int qq = 0; qq < 2; qq++) {
                    float4 v0 = *reinterpret_cast<const float4*>(fp + fo[tt] + qq*32);
                    float4 v1 = *reinterpret_cast<const float4*>(fp + fo[tt] + qq*32 + 16);
                    uint2 h0,l0,h1,l1;
                    splitf4(v0, h0, l0); splitf4(v1, h1, l1);
                    uint32_t dsw = SWZ(r, 2*half + qq);
                    *reinterpret_cast<uint4*>(smc + ho[tt]  + dsw) = make_uint4(h0.x,h0.y,h1.x,h1.y);
                    *reinterpret_cast<uint4*>(smc + lo_[tt] + dsw) = make_uint4(l0.x,l0.y,l1.x,l1.y);
                }
            }
        }
        __syncthreads();
        // compute 2 x k16
#pragma unroll
        for (int k16 = 0; k16 < 2; k16++) {
            const int hc = lane >> 4, br = lane & 15;
            const int cc = k16*2 + hc;
            uint32_t ah[4][4], al[4][4];
#pragma unroll
            for (int i = 0; i < 4; i++) {
                int row = wm*64 + i*16 + br;
                uint32_t off = SWZ(row, cc);
                LDSM4(ah[i][0],ah[i][1],ah[i][2],ah[i][3], sb + GU_TAH + off);
                LDSM4(al[i][0],al[i][1],al[i][2],al[i][3], sb + GU_TAL + off);
            }
#pragma unroll
            for (int p = 0; p < 2; p++) {
                int row = wn*32 + p*16 + br;
                uint32_t off = SWZ(row, cc);
                uint32_t g0,g1,g2,g3, h0,h1,h2,h3, u0,u1,u2,u3, w0,w1,w2,w3;
                LDSM4(g0,g1,g2,g3, sb + GU_TGH + off);
                LDSM4(h0,h1,h2,h3, sb + GU_TGL + off);
                LDSM4(u0,u1,u2,u3, sb + GU_TUH + off);
                LDSM4(w0,w1,w2,w3, sb + GU_TUL + off);
#pragma unroll
                for (int i = 0; i < 4; i++) {
                    MMA_BF16(cg[i][p*2],   ah[i], g0, g2);
                    MMA_BF16(cg[i][p*2],   ah[i], h0, h2);
                    MMA_BF16(cg[i][p*2],   al[i], g0, g2);
                    MMA_BF16(cg[i][p*2+1], ah[i], g1, g3);
                    MMA_BF16(cg[i][p*2+1], ah[i], h1, h3);
                    MMA_BF16(cg[i][p*2+1], al[i], g1, g3);
                    MMA_BF16(cu[i][p*2],   ah[i], u0, u2);
                    MMA_BF16(cu[i][p*2],   ah[i], w0, w2);
                    MMA_BF16(cu[i][p*2],   al[i], u0, u2);
                    MMA_BF16(cu[i][p*2+1], ah[i], u1, u3);
                    MMA_BF16(cu[i][p*2+1], ah[i], w1, w3);
                    MMA_BF16(cu[i][p*2+1], al[i], u1, u3);
                }
            }
        }
        __syncthreads();
    }

    // epilogue: silu(g)*u -> bf16 hi/lo to g_mid
#pragma unroll
    for (int i = 0; i < 4; i++) {
        int r0 = wm*64 + i*16 + (lane >> 2);
#pragma unroll
        for (int hh = 0; hh < 2; hh++) {
            int rr = r0 + hh*8;
            if (m0 + rr < segLen) {
                size_t rowb = (size_t)(seg0 + m0 + rr)*IDIM + n0 + wn*32 + (lane & 3)*2;
#pragma unroll
                for (int j = 0; j < 4; j++) {
                    float gv0 = cg[i][j][hh*2+0], gv1 = cg[i][j][hh*2+1];
                    float uv0 = cu[i][j][hh*2+0], uv1 = cu[i][j][hh*2+1];
                    float v0 = uv0 * gv0 / (1.f + __expf(-gv0));
                    float v1 = uv1 * gv1 / (1.f + __expf(-gv1));
                    __nv_bfloat162 hb = __float22bfloat162_rn(make_float2(v0, v1));
                    float2 hf = __bfloat1622float2(hb);
                    __nv_bfloat162 lb = __float22bfloat162_rn(make_float2(v0 - hf.x, v1 - hf.y));
                    *reinterpret_cast<uint32_t*>(&g_mid_hi[rowb + j*8]) = *reinterpret_cast<uint32_t*>(&hb);
                    *reinterpret_cast<uint32_t*>(&g_mid_lo[rowb + j*8]) = *reinterpret_cast<uint32_t*>(&lb);
                }
            }
        }
    }
}

// ---------------- down bf16x3 mma GEMM ----------------
#define DN_AH(b)  ((b)*16384)
#define DN_AL(b)  ((b)*16384 + 8192)
#define DN_BH 32768
#define DN_BL 40960
#define DN_F32 49152
#define DN_FSTRIDE 18432
#define DN_SMEM (DN_F32 + 2*DN_FSTRIDE)   // 86016

__global__ __launch_bounds__(256,1) void down_mma(const float* __restrict__ Wd) {
    const int e = blockIdx.z;
    const int seg0 = g_offsets[e];
    const int segLen = g_offsets[e+1] - seg0;
    const int m0 = blockIdx.y * 128;
    if (m0 >= segLen) return;
    const int n0 = blockIdx.x * 128;

    extern __shared__ char smc[];
    const uint32_t sb = smem_u32(smc);
    const int t = threadIdx.x, lane = t & 31, wid = t >> 5;
    const int wm = wid >> 2, wn = wid & 3;
    const int r = t & 127, half = t >> 7;

    const size_t slotrow = (size_t)(seg0 + m0 + r);   // padded arrays make OOB rows safe
    const __nv_bfloat16* srcAH = g_mid_hi + slotrow*IDIM + half*16;
    const __nv_bfloat16* srcAL = g_mid_lo + slotrow*IDIM + half*16;
    const float* srcB = Wd + ((size_t)e*HDIM + n0 + r)*IDIM + half*16;
    const uint32_t frow = r*144 + half*64;

    float c[4][4][4] = {};

    // issue stage 0
    {
#pragma unroll
        for (int qq = 0; qq < 2; qq++) {
            uint32_t dsw = SWZ(r, 2*half + qq);
            CPA16(sb + DN_AH(0) + dsw, srcAH + qq*8, 16);
            CPA16(sb + DN_AL(0) + dsw, srcAL + qq*8, 16);
        }
        uint32_t fb = sb + DN_F32 + frow;
#pragma unroll
        for (int q = 0; q < 4; q++) CPA16(fb + q*16, srcB + q*4, 16);
        CPA_COMMIT();
    }

#pragma unroll 1
    for (int s = 0; s < 64; ++s) {
        const int b = s & 1;
        CPA_WAIT0();
        __syncthreads();
        if (s < 63) {
            const int k0 = (s+1)*32;
#pragma unroll
            for (int qq = 0; qq < 2; qq++) {
                uint32_t dsw = SWZ(r, 2*half + qq);
                CPA16(sb + DN_AH(b^1) + dsw, srcAH + k0 + qq*8, 16);
                CPA16(sb + DN_AL(b^1) + dsw, srcAL + k0 + qq*8, 16);
            }
            uint32_t fb = sb + DN_F32 + (b^1)*DN_FSTRIDE + frow;
#pragma unroll
            for (int q = 0; q < 4; q++) CPA16(fb + q*16, srcB + k0 + q*4, 16);
            CPA_COMMIT();
        }
        // convert B fp32 -> bf16 hi/lo
        {
            const char* fp = smc + DN_F32 + b*DN_FSTRIDE + frow;
#pragma unroll
            for (int qq = 0; qq < 2; qq++) {
                float4 v0 = *reinterpret_cast<const float4*>(fp + qq*32);
                float4 v1 = *reinterpret_cast<const float4*>(fp + qq*32 + 16);
                uint2 h0,l0,h1,l1;
                splitf4(v0, h0, l0); splitf4(v1, h1, l1);
                uint32_t dsw = SWZ(r, 2*half + qq);
                *reinterpret_cast<uint4*>(smc + DN_BH + dsw) = make_uint4(h0.x,h0.y,h1.x,h1.y);
                *reinterpret_cast<uint4*>(smc + DN_BL + dsw) = make_uint4(l0.x,l0.y,l1.x,l1.y);
            }
        }
        __syncthreads();
#pragma unroll
        for (int k16 = 0; k16 < 2; k16++) {
            const int hc = lane >> 4, br = lane & 15;
            const int cc = k16*2 + hc;
            uint32_t ah[4][4], al[4][4];
#pragma unroll
            for (int i = 0; i < 4; i++) {
                int row = wm*64 + i*16 + br;
                uint32_t off = SWZ(row, cc);
                LDSM4(ah[i][0],ah[i][1],ah[i][2],ah[i][3], sb + DN_AH(b) + off);
                LDSM4(al[i][0],al[i][1],al[i][2],al[i][3], sb + DN_AL(b) + off);
            }
#pragma unroll
            for (int p = 0; p < 2; p++) {
                int row = wn*32 + p*16 + br;
                uint32_t off = SWZ(row, cc);
                uint32_t b0,b1,b2,b3, d0,d1,d2,d3;
                LDSM4(b0,b1,b2,b3, sb + DN_BH + off);
                LDSM4(d0,d1,d2,d3, sb + DN_BL + off);
#pragma unroll
                for (int i = 0; i < 4; i++) {
                    MMA_BF16(c[i][p*2],   ah[i], b0, b2);
                    MMA_BF16(c[i][p*2],   ah[i], d0, d2);
                    MMA_BF16(c[i][p*2],   al[i], b0, b2);
                    MMA_BF16(c[i][p*2+1], ah[i], b1, b3);
                    MMA_BF16(c[i][p*2+1], ah[i], d1, d3);
                    MMA_BF16(c[i][p*2+1], al[i], b1, b3);
                }
            }
        }
        __syncthreads();
    }

#pragma unroll
    for (int i = 0; i < 4; i++) {
        int r0 = wm*64 + i*16 + (lane >> 2);
#pragma unroll
        for (int hh = 0; hh < 2; hh++) {
            int rr = r0 + hh*8;
            if (m0 + rr < segLen) {
                float* dst = g_down + (size_t)(seg0 + m0 + rr)*HDIM + n0 + wn*32 + (lane & 3)*2;
#pragma unroll
                for (int j = 0; j < 4; j++)
                    *reinterpret_cast<float2*>(dst + j*8) =
                        make_float2(c[i][j][hh*2], c[i][j][hh*2+1]);
            }
        }
    }
}

// ---------------- combine ----------------
__global__ void combine_kernel(float* __restrict__ out) {
    int idx = blockIdx.x * blockDim.x + threadIdx.x;
    if (idx >= NTOK * (HDIM/4)) return;
    int n = idx / (HDIM/4);
    int h = (idx % (HDIM/4)) * 4;
    float w0 = g_topk_w[2*n], w1 = g_topk_w[2*n+1];
    int s0 = g_slot_of[2*n], s1 = g_slot_of[2*n+1];
    float4 a = *reinterpret_cast<const float4*>(&g_down[(size_t)s0*HDIM + h]);
    float4 b = *reinterpret_cast<const float4*>(&g_down[(size_t)s1*HDIM + h]);
    float4 o;
    o.x = w0*a.x + w1*b.x;
    o.y = w0*a.y + w1*b.y;
    o.z = w0*a.z + w1*b.z;
    o.w = w0*a.w + w1*b.w;
    *reinterpret_cast<float4*>(&out[(size_t)n*HDIM + h]) = o;
}

// ---------------- launch ----------------
extern "C" void kernel_launch(void* const* d_in, const int* in_sizes, int n_in,
                              void* d_out, int out_size) {
    const float* x  = (const float*)d_in[0];
    const float* Wr = (const float*)d_in[1];
    const float* Wg = (const float*)d_in[2];
    const float* Wu = (const float*)d_in[3];
    const float* Wd = (const float*)d_in[4];
    float* out = (float*)d_out;

    cudaFuncSetAttribute(gateup_mma, cudaFuncAttributeMaxDynamicSharedMemorySize, GU_SMEM);
    cudaFuncSetAttribute(down_mma,   cudaFuncAttributeMaxDynamicSharedMemorySize, DN_SMEM);

    void* ctr_ptr = nullptr;
    cudaGetSymbolAddress(&ctr_ptr, g_ctr);
    cudaMemsetAsync(ctr_ptr, 0, sizeof(int)*2*NEXP, 0);

    router_kernel<<<NTOK/8, 256>>>(x, Wr);

    float* aux_out = (out_size > NTOK*HDIM) ? (out + (size_t)NTOK*HDIM) : nullptr;
    scan_kernel<<<1, 32>>>(aux_out);

    assign_kernel<<<(NK + 255)/256, 256>>>();

    gateup_mma<<<dim3(IDIM/128, NK/128, NEXP), 256, GU_SMEM>>>(x, Wg, Wu);
    down_mma<<<dim3(HDIM/128, NK/128, NEXP), 256, DN_SMEM>>>(Wd);

    combine_kernel<<<(NTOK*(HDIM/4) + 255)/256, 256>>>(out);
}